// round 3
// baseline (speedup 1.0000x reference)
#include <cuda_runtime.h>
#include <cstdint>
#include <math.h>

// ---------------- problem-scale device scratch (static, no allocation) ----------------
#define NMAX 40960
__device__ float4 g_p4[NMAX];      // x, y, z, |p|^2
__device__ int    g_anchors[8192];
__device__ double g_terms[8192];
__device__ unsigned g_nready;      // anchors published so far (release/acquire)

#define KK 20
#define INFF __int_as_float(0x7f800000)
typedef unsigned long long ull;

// ---------------- prep: SoA float4 with precomputed |p|^2 ----------------
__global__ void prep_kernel(const float* __restrict__ pos, int N) {
    int j = blockIdx.x * blockDim.x + threadIdx.x;
    if (j == 0) g_nready = 0u;
    if (j < N) {
        float x = pos[3*j], y = pos[3*j+1], z = pos[3*j+2];
        float n2 = __fadd_rn(__fadd_rn(__fmul_rn(x,x), __fmul_rn(y,y)), __fmul_rn(z,z));
        g_p4[j] = make_float4(x, y, z, n2);
    }
}

// ---------------- fused FPS (cluster 0) + KNN/loss (CTAs 8..135) ----------------
#define FCT  8
#define FTPB 512
#define FTOT (FCT*FTPB)   // 4096 threads
#define FP   10           // ceil(40000/4096)
#define NPAIR (FP/2)
#define KNN_CTAS 128
#define TOTAL_CTAS (FCT + KNN_CTAS)
#define KNN_WARPS (KNN_CTAS * (FTPB/32))   // 2048

__device__ __forceinline__ unsigned fps_mapa(unsigned addr, unsigned rank) {
    unsigned r;
    asm("mapa.shared::cluster.u32 %0, %1, %2;" : "=r"(r) : "r"(addr), "r"(rank));
    return r;
}
__device__ __forceinline__ unsigned smem_u32_(const void* p) {
    return (unsigned)__cvta_generic_to_shared(p);
}
__device__ __forceinline__ void cluster_sync_() {
    asm volatile("barrier.cluster.arrive.aligned;\n\tbarrier.cluster.wait.aligned;" ::: "memory");
}
__device__ __forceinline__ ull pack2(float lo, float hi) {
    ull v; asm("mov.b64 %0, {%1, %2};" : "=l"(v) : "r"(__float_as_uint(lo)), "r"(__float_as_uint(hi)));
    return v;
}
__device__ __forceinline__ void unpack2(ull v, float &lo, float &hi) {
    unsigned a, b; asm("mov.b64 {%0, %1}, %2;" : "=r"(a), "=r"(b) : "l"(v));
    lo = __uint_as_float(a); hi = __uint_as_float(b);
}
__device__ __forceinline__ ull add2_(ull a, ull b) {
    ull d; asm("add.rn.f32x2 %0, %1, %2;" : "=l"(d) : "l"(a), "l"(b)); return d;
}
__device__ __forceinline__ ull mul2_(ull a, ull b) {
    ull d; asm("mul.rn.f32x2 %0, %1, %2;" : "=l"(d) : "l"(a), "l"(b)); return d;
}
__device__ __forceinline__ ull fma2_(ull a, ull b, ull c) {
    ull d; asm("fma.rn.f32x2 %0, %1, %2, %3;" : "=l"(d) : "l"(a), "l"(b), "l"(c)); return d;
}
__device__ __forceinline__ double wsum_d(double v) {
    #pragma unroll
    for (int o = 16; o > 0; o >>= 1) v += __shfl_xor_sync(0xFFFFFFFFu, v, o);
    return v;
}

__global__ void __cluster_dims__(FCT,1,1) __launch_bounds__(FTPB,1)
fused_kernel(const float* __restrict__ vec_pred, int N, int nA) {
    extern __shared__ float4 s_pts[];          // FPS: [FTPB*FP] point mirror
    __shared__ ull      s_wkey[FTPB/32];
    __shared__ ull      s_xkey[2][FCT];        // exchanged keys (double buffered)
    __shared__ float4   s_xpos[2][FCT];        // exchanged winner positions
    __shared__ unsigned s_seq[2][FCT];         // per-rank round tags

    int tid  = threadIdx.x;
    int lane = tid & 31, wid = tid >> 5;

    if (blockIdx.x < FCT) {
        // ================= FPS role (cluster 0) =================
        unsigned rank; asm("mov.u32 %0, %%cluster_ctarank;" : "=r"(rank));
        int gt = (int)rank * FTPB + tid;

        if (tid < 2*FCT) ((unsigned*)s_seq)[tid] = 0u;

        ull X2[NPAIR], Y2[NPAIR], Z2[NPAIR];
        float md[FP];
        bool has10 = (9*FTOT + gt) < N;

        float4 a0 = g_p4[0];
        float bv = -1.0f; int bi = 0;
        float xs[FP], ys[FP], zs[FP];
        #pragma unroll
        for (int s = 0; s < FP; s++) {
            int gi = s*FTOT + gt;
            float4 q = g_p4[gi];
            s_pts[tid*FP + s] = q;
            xs[s]=q.x; ys[s]=q.y; zs[s]=q.z;
            float dx=q.x-a0.x, dy=q.y-a0.y, dz=q.z-a0.z;
            float d = fmaf(dx,dx, fmaf(dy,dy, dz*dz));
            bool valid = (s < 9) || has10;
            md[s] = valid ? d : -1.0f;
            if (valid && d > bv) { bv = d; bi = gi; }
        }
        #pragma unroll
        for (int p = 0; p < NPAIR; p++) {
            X2[p] = pack2(xs[2*p], xs[2*p+1]);
            Y2[p] = pack2(ys[2*p], ys[2*p+1]);
            Z2[p] = pack2(zs[2*p], zs[2*p+1]);
        }
        if (rank == 0 && tid == 0) {
            g_anchors[0] = 0;
            asm volatile("st.release.gpu.global.u32 [%0], %1;" :: "l"(&g_nready), "r"(1u) : "memory");
        }
        __syncthreads();      // s_pts + s_seq ready (CTA-local)
        cluster_sync_();      // everything visible cluster-wide

        for (int it = 1; it < nA; ++it) {
            int buf = it & 1;
            unsigned tag = (unsigned)it;

            // ---- warp stage: REDUX argmax (max value, min index on tie) ----
            unsigned vb   = __float_as_uint(bv);
            unsigned wmax = __reduce_max_sync(0xFFFFFFFFu, vb);
            unsigned cand = (vb == wmax) ? (unsigned)bi : 0xFFFFFFFFu;
            unsigned wmin = __reduce_min_sync(0xFFFFFFFFu, cand);
            ull mykey = ((ull)wmax << 32) | (0xFFFFFFFFu - wmin);
            if (wid != 0 && vb == wmax && (unsigned)bi == wmin) s_wkey[wid] = mykey;
            __syncthreads();   // (A) s_wkey published

            if (wid == 0) {
                // ---- block stage over 16 warp keys (warp0's own key from register) ----
                ull k = (lane > 0 && lane < FTPB/32) ? s_wkey[lane] : (lane == 0 ? mykey : 0ull);
                unsigned kv   = (unsigned)(k >> 32);
                unsigned bmax = __reduce_max_sync(0xFFFFFFFFu, kv);
                unsigned cenc = (kv == bmax) ? (unsigned)(k & 0xFFFFFFFFu) : 0u;
                unsigned benc = __reduce_max_sync(0xFFFFFFFFu, cenc);
                if (lane < FCT) {
                    ull blkkey = ((ull)bmax << 32) | benc;
                    unsigned blkidx = 0xFFFFFFFFu - benc;
                    int tloc = (int)(blkidx & (FTOT-1)) - (int)rank * FTPB;
                    int sIdx = (int)(blkidx >> 12);
                    float4 bp = s_pts[tloc*FP + sIdx];
                    // lane r ships this CTA's partial to cluster rank r
                    unsigned kaddr = fps_mapa(smem_u32_(&s_xkey[buf][rank]), (unsigned)lane);
                    unsigned paddr = fps_mapa(smem_u32_(&s_xpos[buf][rank]), (unsigned)lane);
                    unsigned saddr = fps_mapa(smem_u32_(&s_seq[buf][rank]),  (unsigned)lane);
                    ull xy = pack2(bp.x, bp.y);
                    asm volatile("st.shared::cluster.u64 [%0], %1;" :: "r"(kaddr), "l"(blkkey) : "memory");
                    asm volatile("st.shared::cluster.u64 [%0], %1;" :: "r"(paddr), "l"(xy)     : "memory");
                    asm volatile("st.shared::cluster.u32 [%0], %1;" :: "r"(paddr + 8), "r"(__float_as_uint(bp.z)) : "memory");
                    asm volatile("st.release.cluster.shared::cluster.u32 [%0], %1;" :: "r"(saddr), "r"(tag) : "memory");
                }
                // ---- warp0 polls its own 8 seq words (lane r -> word r) ----
                if (lane < FCT) {
                    unsigned sa = smem_u32_(&s_seq[buf][lane]);
                    unsigned sv;
                    do {
                        asm volatile("ld.acquire.cluster.shared::cta.u32 %0, [%1];" : "=r"(sv) : "r"(sa) : "memory");
                    } while (sv != tag);
                }
                __syncwarp();
            }
            __syncthreads();   // (B) exchange complete; acquire propagated CTA-wide

            // ---- consume: max over 8 keys (keys unique), track rank ----
            ull k0=s_xkey[buf][0], k1=s_xkey[buf][1], k2=s_xkey[buf][2], k3=s_xkey[buf][3];
            ull k4=s_xkey[buf][4], k5=s_xkey[buf][5], k6=s_xkey[buf][6], k7=s_xkey[buf][7];
            ull ka = k0; int ra = 0; if (k1 > ka) { ka = k1; ra = 1; }
            ull kb = k2; int rb = 2; if (k3 > kb) { kb = k3; rb = 3; }
            ull kc = k4; int rc = 4; if (k5 > kc) { kc = k5; rc = 5; }
            ull kd = k6; int rd = 6; if (k7 > kd) { kd = k7; rd = 7; }
            if (kb > ka) { ka = kb; ra = rb; }
            if (kd > kc) { kc = kd; rc = rd; }
            if (kc > ka) { ka = kc; ra = rc; }
            float4 ap = s_xpos[buf][ra];
            if (rank == 0 && tid == 0) {
                g_anchors[it] = (int)(0xFFFFFFFFu - (unsigned)ka);
                asm volatile("st.release.gpu.global.u32 [%0], %1;" :: "l"(&g_nready), "r"((unsigned)(it+1)) : "memory");
            }

            // ---- update min-distances (f32x2 packed) + local argmax ----
            ull nax = pack2(-ap.x, -ap.x), nay = pack2(-ap.y, -ap.y), naz = pack2(-ap.z, -ap.z);
            #pragma unroll
            for (int p = 0; p < NPAIR; p++) {
                ull dx2 = add2_(X2[p], nax);
                ull dy2 = add2_(Y2[p], nay);
                ull dz2 = add2_(Z2[p], naz);
                ull dd  = fma2_(dx2, dx2, fma2_(dy2, dy2, mul2_(dz2, dz2)));
                float dlo, dhi; unpack2(dd, dlo, dhi);
                md[2*p]   = fminf(md[2*p],   dlo);
                md[2*p+1] = fminf(md[2*p+1], dhi);
            }
            bv = md[0]; bi = gt;
            #pragma unroll
            for (int s = 1; s < 9; s++) {
                if (md[s] > bv) { bv = md[s]; bi = gt + s*FTOT; }
            }
            if (has10 && md[9] > bv) { bv = md[9]; bi = gt + 9*FTOT; }
        }
        cluster_sync_();   // keep cluster alive until all peers consumed
    } else {
        // ================= KNN + PCA + loss role =================
        int kcta = blockIdx.x - FCT;                   // 0..127
        int w    = kcta * (FTPB/32) + wid;             // global KNN warp id

        for (int i = w; i < nA; i += KNN_WARPS) {
            // wait until anchor i published
            if (lane == 0) {
                unsigned c;
                for (;;) {
                    asm volatile("ld.acquire.gpu.global.u32 %0, [%1];" : "=r"(c) : "l"(&g_nready) : "memory");
                    if (c > (unsigned)i) break;
                    __nanosleep(((unsigned)i - c > 64u) ? 2000u : 200u);
                }
            }
            __syncwarp();

            int a = g_anchors[i];
            float4 ap = g_p4[a];
            float na2 = ap.w;

            float vv[KK]; int ii[KK];
            #pragma unroll
            for (int k = 0; k < KK; k++) { vv[k] = INFF; ii[k] = 0x7fffffff; }

            int steps = N >> 5;
            #pragma unroll 4
            for (int s = 0; s < steps; s++) {
                int j = (s << 5) + lane;
                float4 q = g_p4[j];
                float dot = fmaf(ap.z, q.z, fmaf(ap.y, q.y, ap.x*q.x));
                float d2 = (na2 - 2.0f*dot) + q.w;           // reference's expansion
                if (d2 < vv[KK-1]) {
                    float cd = d2; int cj = j;
                    #pragma unroll
                    for (int k = 0; k < KK; k++) {
                        if (cd < vv[k]) { float tv=vv[k]; int ti=ii[k]; vv[k]=cd; ii[k]=cj; cd=tv; cj=ti; }
                    }
                }
            }
            int rem = N - (steps << 5);
            if (rem > 0 && lane < rem) {
                int j = (steps << 5) + lane;
                float4 q = g_p4[j];
                float dot = fmaf(ap.z, q.z, fmaf(ap.y, q.y, ap.x*q.x));
                float d2 = (na2 - 2.0f*dot) + q.w;
                if (d2 < vv[KK-1]) {
                    float cd = d2; int cj = j;
                    #pragma unroll
                    for (int k = 0; k < KK; k++) {
                        if (cd < vv[k]) { float tv=vv[k]; int ti=ii[k]; vv[k]=cd; ii[k]=cj; cd=tv; cj=ti; }
                    }
                }
            }

            // 20-round warp merge; ties -> lower index (matches jax top_k)
            int nbr = -1;
            for (int r = 0; r < KK; r++) {
                unsigned m = __float_as_uint(vv[0]);
                m = (m & 0x80000000u) ? ~m : (m | 0x80000000u);
                ull key = ((ull)m << 32) | (unsigned)ii[0];
                #pragma unroll
                for (int o = 16; o > 0; o >>= 1) {
                    ull k2 = __shfl_xor_sync(0xFFFFFFFFu, key, o);
                    if (k2 < key) key = k2;
                }
                int widx = (int)(unsigned)key;
                if (lane == r) nbr = widx;
                if (ii[0] == widx) {
                    #pragma unroll
                    for (int k = 0; k < KK-1; k++) { vv[k]=vv[k+1]; ii[k]=ii[k+1]; }
                    vv[KK-1] = INFF; ii[KK-1] = 0x7fffffff;
                }
            }

            // covariance in double over 20 neighbors
            double x=0.0, y=0.0, z=0.0;
            if (lane < KK) { float4 q = g_p4[nbr]; x=q.x; y=q.y; z=q.z; }
            double sx = wsum_d(x), sy = wsum_d(y), sz = wsum_d(z);
            double mx = sx/KK, my = sy/KK, mz = sz/KK;
            double cx = (lane<KK) ? x-mx : 0.0;
            double cy = (lane<KK) ? y-my : 0.0;
            double cz = (lane<KK) ? z-mz : 0.0;
            double xx = wsum_d(cx*cx), xy = wsum_d(cx*cy), xz = wsum_d(cx*cz);
            double yy = wsum_d(cy*cy), yz = wsum_d(cy*cz), zz = wsum_d(cz*cz);

            if (lane == 0) {
                double A=xx, B=yy, C=zz, D=xy, E=xz, F=yz;
                double p1 = D*D + E*E + F*F;
                double q3 = (A+B+C)/3.0;
                double p2 = (A-q3)*(A-q3) + (B-q3)*(B-q3) + (C-q3)*(C-q3) + 2.0*p1;
                double p  = sqrt(p2/6.0);
                double lam;
                if (p > 0.0) {
                    double ip = 1.0/p;
                    double b00=(A-q3)*ip, b11=(B-q3)*ip, b22=(C-q3)*ip;
                    double b01=D*ip, b02=E*ip, b12=F*ip;
                    double det = b00*(b11*b22 - b12*b12)
                               - b01*(b01*b22 - b12*b02)
                               + b02*(b01*b12 - b11*b02);
                    double rr = det*0.5;
                    rr = fmin(1.0, fmax(-1.0, rr));
                    lam = q3 + 2.0*p*cos(acos(rr)/3.0);
                } else lam = q3;

                double r0x=A-lam, r0y=D,     r0z=E;
                double r1x=D,     r1y=B-lam, r1z=F;
                double r2x=E,     r2y=F,     r2z=C-lam;
                double c1x=r0y*r1z-r0z*r1y, c1y=r0z*r1x-r0x*r1z, c1z=r0x*r1y-r0y*r1x;
                double c2x=r0y*r2z-r0z*r2y, c2y=r0z*r2x-r0x*r2z, c2z=r0x*r2y-r0y*r2x;
                double c3x=r1y*r2z-r1z*r2y, c3y=r1z*r2x-r1x*r2z, c3z=r1x*r2y-r1y*r2x;
                double n1=c1x*c1x+c1y*c1y+c1z*c1z;
                double n2=c2x*c2x+c2y*c2y+c2z*c2z;
                double n3=c3x*c3x+c3y*c3y+c3z*c3z;
                double vx=c1x, vy=c1y, vz=c1z, bn=n1;
                if (n2 > bn) { vx=c2x; vy=c2y; vz=c2z; bn=n2; }
                if (n3 > bn) { vx=c3x; vy=c3y; vz=c3z; bn=n3; }
                if (bn < 1e-300) { vx=1.0; vy=0.0; vz=0.0; bn=1.0; }
                double inv = rsqrt(bn);
                vx*=inv; vy*=inv; vz*=inv;

                const float* vp = vec_pred + 3*i;
                double ax=vp[0], ay=vp[1], az=vp[2];
                double nrm = sqrt(ax*ax + ay*ay + az*az);
                if (nrm < 1e-8) nrm = 1e-8;
                double dt = ax*vx + ay*vy + az*vz;
                double ac = fabs(dt)/nrm;
                g_terms[i] = log(ac + 1e-6);
            }
        }
    }
}

// ---------------- final deterministic reduction ----------------
__global__ void reduce_kernel(int nA, float* __restrict__ out) {
    __shared__ double sm[32];
    int tid = threadIdx.x;
    double s = 0.0;
    for (int i = tid; i < nA; i += blockDim.x) s += g_terms[i];
    s = wsum_d(s);
    if ((tid & 31) == 0) sm[tid >> 5] = s;
    __syncthreads();
    if (tid < 32) {
        double v = (tid < (int)(blockDim.x >> 5)) ? sm[tid] : 0.0;
        v = wsum_d(v);
        if (tid == 0) out[0] = (float)(-v / (double)nA);
    }
}

// ---------------- launch ----------------
extern "C" void kernel_launch(void* const* d_in, const int* in_sizes, int n_in,
                              void* d_out, int out_size) {
    const float* vec_pred = (const float*)d_in[0];
    const float* pos      = (const float*)d_in[1];
    int N  = in_sizes[1] / 3;
    int nA = (int)ceil(0.1 * (double)N);

    int smem = FTPB * FP * (int)sizeof(float4);   // 80 KB point mirror
    cudaFuncSetAttribute(fused_kernel, cudaFuncAttributeMaxDynamicSharedMemorySize, smem);

    prep_kernel<<<(N + 255)/256, 256>>>(pos, N);
    fused_kernel<<<TOTAL_CTAS, FTPB, smem>>>(vec_pred, N, nA);
    reduce_kernel<<<1, 512>>>(nA, (float*)d_out);
}